// round 16
// baseline (speedup 1.0000x reference)
#include <cuda_runtime.h>
#include <cuda_fp16.h>
#include <cstdint>

#define NN   50000
#define NE   800000
#define NG   64
#define CH   64
#define INCH 128
#define SCAN_B 1024
#define NB   ((NN + SCAN_B - 1) / SCAN_B)   // 49
#define TB   256
#define GTILES ((NN + 63) / 64)             // 782
#define EB4  ((NE + TB * 4 - 1) / (TB * 4)) // 782 edge-blocks at 4 edges/thread
#define SCALE_BLOCKS ((NN * 16 + TB - 1) / TB)  // 3125

// ---------------- scratch (static device globals; no allocation) -------------
struct ZeroBlk {
    unsigned long long pd[NN];          // count<<40 | wdeg fixed-point
    unsigned maxk[NG * CH];             // ukey-max accumulator (0 = -inf)
    float    sum[NG * CH];
    float    cnt[NG];
    unsigned done;
};
__device__ ZeroBlk g_z;
__device__ float g_dinv[NN];
__device__ int   g_rowptr[NN + 1];
__device__ int   g_fill[NN];
__device__ int   g_bsum[64];
__device__ int2  g_edge[NE];                   // CSR-sorted (src, w-bits)
__device__ __align__(16) __half g_h[NN * CH];  // h' = dinv * (act @ W), fp16
__device__ __align__(16) float g_act[NN * CH]; // tanh(layer output), fp32

// ---------------- helpers ----------------------------------------------------
// tanh = 1 - 2/(1+e^{2x}); exact limits at +-inf, ~1e-7 abs err. 6 instrs.
__device__ __forceinline__ float acc_tanh(float x) {
    float t = __expf(2.0f * x);
    return 1.0f - __fdividef(2.0f, t + 1.0f);
}
__device__ __forceinline__ unsigned ukey(float f) {
    unsigned u = __float_as_uint(f);
    return (u & 0x80000000u) ? ~u : (u | 0x80000000u);
}
__device__ __forceinline__ float udec(unsigned u) {
    return __uint_as_float((u & 0x80000000u) ? (u & 0x7FFFFFFFu) : ~u);
}

#define FMA2(d, a, b) asm("fma.rn.f32x2 %0, %1, %2, %0;" : "+l"(d) : "l"(a), "l"(b))
__device__ __forceinline__ unsigned long long pack2(float x) {
    unsigned long long r;
    unsigned xi = __float_as_uint(x);
    asm("mov.b64 %0, {%1, %1};" : "=l"(r) : "r"(xi));
    return r;
}
__device__ __forceinline__ float2 unpack2(unsigned long long v) {
    unsigned lo, hi;
    asm("mov.b64 {%0, %1}, %2;" : "=r"(lo), "=r"(hi) : "l"(v));
    return make_float2(__uint_as_float(lo), __uint_as_float(hi));
}
__device__ __forceinline__ unsigned h2_to_u(__half2 h) {
    return *reinterpret_cast<unsigned*>(&h);
}
__device__ __forceinline__ __half2 u_to_h2(unsigned u) {
    return *reinterpret_cast<__half2*>(&u);
}

// ---------------- preprocessing ----------------------------------------------
__global__ void k_scan_block() {
    __shared__ int wsum[32];
    int tid = threadIdx.x;
    int i   = blockIdx.x * SCAN_B + tid;
    int lane = tid & 31, wid = tid >> 5;
    unsigned long long pd = (i < NN) ? g_z.pd[i] : 0ull;
    int v = (int)(pd >> 40);
    int s = v;
#pragma unroll
    for (int o = 1; o < 32; o <<= 1) {
        int t = __shfl_up_sync(0xFFFFFFFFu, s, o);
        if (lane >= o) s += t;
    }
    if (lane == 31) wsum[wid] = s;
    __syncthreads();
    if (wid == 0) {
        int ws = wsum[lane];
#pragma unroll
        for (int o = 1; o < 32; o <<= 1) {
            int t = __shfl_up_sync(0xFFFFFFFFu, ws, o);
            if (lane >= o) ws += t;
        }
        wsum[lane] = ws;
    }
    __syncthreads();
    int off = wid ? wsum[wid - 1] : 0;
    if (i < NN) {
        int rp = off + s - v;          // exclusive, pre-carry
        g_rowptr[i] = rp;
        g_fill[i]   = rp;
        float wdeg = (float)(pd & ((1ull << 40) - 1ull)) * (1.0f / 2097152.0f);
        g_dinv[i] = rsqrtf(wdeg + 1.0f);   // +1 self-loop weight
    }
    if (tid == SCAN_B - 1) g_bsum[blockIdx.x] = off + s;
}

// fused: blocks [0, EB4) place edges (4/thread, MLP-deep); rest do layer-0 scale.
__global__ void k_scale_place(const int* __restrict__ ei, const float* __restrict__ w) {
    int tid = threadIdx.x;
    if (blockIdx.x < EB4) {
        __shared__ int sc[64];
        if (tid < 32) {
            int v0 = (2 * tid     < NB) ? g_bsum[2 * tid]     : 0;
            int v1 = (2 * tid + 1 < NB) ? g_bsum[2 * tid + 1] : 0;
            int p = v0 + v1;
            int s = p;
#pragma unroll
            for (int o = 1; o < 32; o <<= 1) {
                int t = __shfl_up_sync(0xFFFFFFFFu, s, o);
                if (tid >= o) s += t;
            }
            sc[2 * tid]     = s - p;
            sc[2 * tid + 1] = s - p + v0;
        }
        __syncthreads();

        int base = blockIdx.x * (TB * 4) + tid;
        int src[4], dst[4]; float wv[4]; bool ok[4];
#pragma unroll
        for (int i = 0; i < 4; ++i) {
            int e = base + i * TB;
            ok[i] = (e < NE);
            if (ok[i]) { src[i] = ei[e]; dst[i] = ei[NE + e]; wv[i] = w[e]; }
        }
        int pos[4];
#pragma unroll
        for (int i = 0; i < 4; ++i)
            if (ok[i]) pos[i] = atomicAdd(&g_fill[dst[i]], 1) + sc[dst[i] >> 10];
#pragma unroll
        for (int i = 0; i < 4; ++i)
            if (ok[i]) g_edge[pos[i]] = make_int2(src[i], __float_as_int(wv[i]));

        // finalize rowptr (carry applied exactly once; EB4*TB = 200192 >= NN)
        int gt = blockIdx.x * TB + tid;
        if (gt < NN) g_rowptr[gt] += sc[gt >> 10];
        if (gt == 0) g_rowptr[NN] = NE;
    } else {
        // layer-0 deferred scale: g_h = fp16(dinv * g_act)
        int i = (blockIdx.x - EB4) * TB + tid;
        if (i >= NN * 16) return;
        int node = i >> 4;
        int c4 = (i & 15) * 4;
        float dv = g_dinv[node];
        float4 v = *(const float4*)(g_act + (size_t)node * CH + c4);
        uint2 st;
        st.x = h2_to_u(__float22half2_rn(make_float2(v.x * dv, v.y * dv)));
        st.y = h2_to_u(__float22half2_rn(make_float2(v.z * dv, v.w * dv)));
        *(uint2*)(g_h + (size_t)node * CH + c4) = st;
    }
}

// ------- GEMM (full-K single-stage smem, f32x2 FMA) ----------------------------
// FUSE_PRE: blocks >= GTILES run degree accumulation (4 edges/thread).
// RAW_OUT: write unscaled fp32 h to g_act (layer 0; dinv applied by k_scale_place).
template <int K, bool FROM_ACT, bool FUSE_PRE, bool RAW_OUT>
__global__ void __launch_bounds__(256, (K == 128 ? 3 : 4))
k_gemm(const float* __restrict__ in, const float* __restrict__ W,
       const int* __restrict__ ei, const float* __restrict__ ea) {
    constexpr int KP = K + 4;                 // padded A stride (16B multiple)
    __shared__ __align__(16) float sA[64 * KP];
    __shared__ __align__(16) float sW[K * 64];

    const int tid = threadIdx.x;

    if (FUSE_PRE && blockIdx.x >= GTILES) {
        int base = (blockIdx.x - GTILES) * (TB * 4) + tid;
        int dst[4]; unsigned long long v[4]; bool ok[4];
#pragma unroll
        for (int i = 0; i < 4; ++i) {
            int e = base + i * TB;
            ok[i] = (e < NE);
            if (ok[i]) {
                dst[i] = ei[NE + e];
                v[i] = (1ull << 40) |
                    (unsigned long long)__float2uint_rn(ea[e] * 2097152.0f);
            }
        }
#pragma unroll
        for (int i = 0; i < 4; ++i)
            if (ok[i]) atomicAdd(&g_z.pd[dst[i]], v[i]);
        return;
    }

    const int row0 = blockIdx.x * 64;
    const int rowg = tid >> 4;    // 0..15, 4 rows each
    const int colg = tid & 15;    // 0..15, 4 cols each

    const float* A = FROM_ACT ? (const float*)g_act : in;

    // stage full A tile (64 x K) and W (K x 64): deep MLP, one sync
#pragma unroll
    for (int idx = tid; idx < 64 * (K / 4); idx += TB) {
        int rr = idx / (K / 4), k4 = (idx % (K / 4)) * 4;
        int grow = row0 + rr;
        float4 v = make_float4(0.f, 0.f, 0.f, 0.f);
        if (grow < NN) v = *(const float4*)(A + (size_t)grow * K + k4);
        *(float4*)(sA + rr * KP + k4) = v;
    }
#pragma unroll
    for (int idx = tid; idx < K * 16; idx += TB) {
        int rr = idx >> 4, c4 = (idx & 15) * 4;
        *(float4*)(sW + rr * 64 + c4) = *(const float4*)(W + (size_t)rr * 64 + c4);
    }
    __syncthreads();

    unsigned long long acc[4][2] = {{0ull,0ull},{0ull,0ull},{0ull,0ull},{0ull,0ull}};

#pragma unroll
    for (int k = 0; k < K; k += 4) {
        float4 a0 = *(const float4*)(sA + (rowg * 4 + 0) * KP + k);
        float4 a1 = *(const float4*)(sA + (rowg * 4 + 1) * KP + k);
        float4 a2 = *(const float4*)(sA + (rowg * 4 + 2) * KP + k);
        float4 a3 = *(const float4*)(sA + (rowg * 4 + 3) * KP + k);
#pragma unroll
        for (int j = 0; j < 4; ++j) {
            const ulonglong2 wv = *(const ulonglong2*)(sW + (k + j) * 64 + colg * 4);
            float e0 = j == 0 ? a0.x : j == 1 ? a0.y : j == 2 ? a0.z : a0.w;
            float e1 = j == 0 ? a1.x : j == 1 ? a1.y : j == 2 ? a1.z : a1.w;
            float e2 = j == 0 ? a2.x : j == 1 ? a2.y : j == 2 ? a2.z : a2.w;
            float e3 = j == 0 ? a3.x : j == 1 ? a3.y : j == 2 ? a3.z : a3.w;
            unsigned long long p0 = pack2(e0), p1 = pack2(e1);
            unsigned long long p2 = pack2(e2), p3 = pack2(e3);
            FMA2(acc[0][0], p0, wv.x); FMA2(acc[0][1], p0, wv.y);
            FMA2(acc[1][0], p1, wv.x); FMA2(acc[1][1], p1, wv.y);
            FMA2(acc[2][0], p2, wv.x); FMA2(acc[2][1], p2, wv.y);
            FMA2(acc[3][0], p3, wv.x); FMA2(acc[3][1], p3, wv.y);
        }
    }

    int row = row0 + rowg * 4;
#pragma unroll
    for (int i = 0; i < 4; ++i) {
        if (row + i < NN) {
            float2 lo = unpack2(acc[i][0]);
            float2 hi = unpack2(acc[i][1]);
            if (RAW_OUT) {
                *(float4*)(g_act + (size_t)(row + i) * CH + colg * 4) =
                    make_float4(lo.x, lo.y, hi.x, hi.y);
            } else {
                float dv = g_dinv[row + i];
                lo.x *= dv; lo.y *= dv; hi.x *= dv; hi.y *= dv;
                uint2 st;
                st.x = h2_to_u(__float22half2_rn(lo));
                st.y = h2_to_u(__float22half2_rn(hi));
                *(uint2*)(g_h + (size_t)(row + i) * CH + colg * 4) = st;
            }
        }
    }
}

// --- gather: act[i] = tanh(b + dv_i*(sum_e w_e*h'[src] + h'[i])) ---------------
// one warp per node; 2-edge half-warp layout (r14), manually 4-pair unrolled:
// phase 1 loads 4 edge records (uniform), phase 2 issues 4 independent h-row
// loads (MLP=4/thread), phase 3 does the FMAs. lane = (half, c4).
__global__ void k_gather(const float* __restrict__ b) {
    int warp = (blockIdx.x * blockDim.x + threadIdx.x) >> 5;
    int lane = threadIdx.x & 31;
    if (warp >= NN) return;
    const int node = warp;
    const int beg  = g_rowptr[node];
    const int deg  = g_rowptr[node + 1] - beg;
    const int half = lane >> 4;
    const int c4   = (lane & 15) * 4;

    float ax = 0.f, ay = 0.f, az = 0.f, aw = 0.f;
    const int np = deg >> 1;
    int j = 0;
    for (; j + 4 <= np; j += 4) {
        const int p = beg + 2 * j + half;
        int2 e0 = g_edge[p];
        int2 e1 = g_edge[p + 2];
        int2 e2 = g_edge[p + 4];
        int2 e3 = g_edge[p + 6];
        uint2 h0 = *(const uint2*)(g_h + (size_t)e0.x * CH + c4);
        uint2 h1 = *(const uint2*)(g_h + (size_t)e1.x * CH + c4);
        uint2 h2 = *(const uint2*)(g_h + (size_t)e2.x * CH + c4);
        uint2 h3 = *(const uint2*)(g_h + (size_t)e3.x * CH + c4);
        float n0 = __int_as_float(e0.y), n1 = __int_as_float(e1.y);
        float n2 = __int_as_float(e2.y), n3 = __int_as_float(e3.y);
        float2 f;
        f = __half22float2(u_to_h2(h0.x)); ax += n0 * f.x; ay += n0 * f.y;
        f = __half22float2(u_to_h2(h0.y)); az += n0 * f.x; aw += n0 * f.y;
        f = __half22float2(u_to_h2(h1.x)); ax += n1 * f.x; ay += n1 * f.y;
        f = __half22float2(u_to_h2(h1.y)); az += n1 * f.x; aw += n1 * f.y;
        f = __half22float2(u_to_h2(h2.x)); ax += n2 * f.x; ay += n2 * f.y;
        f = __half22float2(u_to_h2(h2.y)); az += n2 * f.x; aw += n2 * f.y;
        f = __half22float2(u_to_h2(h3.x)); ax += n3 * f.x; ay += n3 * f.y;
        f = __half22float2(u_to_h2(h3.y)); az += n3 * f.x; aw += n3 * f.y;
    }
    for (; j < np; ++j) {
        int2 e = g_edge[beg + 2 * j + half];
        float ne = __int_as_float(e.y);
        uint2 hv = *(const uint2*)(g_h + (size_t)e.x * CH + c4);
        float2 f0 = __half22float2(u_to_h2(hv.x));
        float2 f1 = __half22float2(u_to_h2(hv.y));
        ax += ne * f0.x; ay += ne * f0.y; az += ne * f1.x; aw += ne * f1.y;
    }
    if (deg & 1) {
        int2 e = g_edge[beg + deg - 1];
        float ne = half ? 0.0f : __int_as_float(e.y);   // avoid double count
        uint2 hv = *(const uint2*)(g_h + (size_t)e.x * CH + c4);
        float2 f0 = __half22float2(u_to_h2(hv.x));
        float2 f1 = __half22float2(u_to_h2(hv.y));
        ax += ne * f0.x; ay += ne * f0.y; az += ne * f1.x; aw += ne * f1.y;
    }
    ax += __shfl_xor_sync(0xFFFFFFFFu, ax, 16);
    ay += __shfl_xor_sync(0xFFFFFFFFu, ay, 16);
    az += __shfl_xor_sync(0xFFFFFFFFu, az, 16);
    aw += __shfl_xor_sync(0xFFFFFFFFu, aw, 16);

    if (half == 0) {
        float dv = g_dinv[node];
        uint2 hu = *(const uint2*)(g_h + (size_t)node * CH + c4);
        float2 h0 = __half22float2(u_to_h2(hu.x));
        float2 h1 = __half22float2(u_to_h2(hu.y));
        float4 bb = *(const float4*)(b + c4);
        float4 o;
        o.x = acc_tanh(bb.x + dv * (ax + h0.x));
        o.y = acc_tanh(bb.y + dv * (ay + h0.y));
        o.z = acc_tanh(bb.z + dv * (az + h1.x));
        o.w = acc_tanh(bb.w + dv * (aw + h1.y));
        *(float4*)(g_act + (size_t)node * CH + c4) = o;
    }
}

// ---------------- pooling + fused head (g_z memset to 0) -----------------------
__device__ __forceinline__ void pool_flush(int g, int c, float mx, float sm, int cnt) {
    if (g < 0) return;
    atomicMax(&g_z.maxk[g * CH + c], ukey(mx));
    atomicAdd(&g_z.sum[g * CH + c], sm);
    if (c == 0) atomicAdd(&g_z.cnt[g], (float)cnt);
}

__global__ void k_pool(const int* __restrict__ batch,
                       const float* __restrict__ Wout,
                       const float* __restrict__ bout,
                       float* __restrict__ out) {
    int tid = threadIdx.x;
    int c  = tid & 63;
    int rs = tid >> 6;           // 0..3
    int base = blockIdx.x * 64;

    int curg = -1; float mx = -3.4e38f, sm = 0.0f; int cnt = 0;
    for (int r = rs; r < 64; r += 4) {
        int node = base + r;
        if (node >= NN) break;
        int g = batch[node];
        float v = g_act[(size_t)node * CH + c];
        if (g != curg) {
            pool_flush(curg, c, mx, sm, cnt);
            curg = g; mx = v; sm = v; cnt = 1;
        } else {
            mx = fmaxf(mx, v); sm += v; cnt++;
        }
    }
    pool_flush(curg, c, mx, sm, cnt);

    // last-block head
    __threadfence();
    __shared__ int s_last;
    __syncthreads();
    if (tid == 0) {
        unsigned t = atomicAdd(&g_z.done, 1u);
        s_last = (t == gridDim.x - 1) ? 1 : 0;
    }
    __syncthreads();
    if (!s_last) return;
    __threadfence();

    __shared__ float sh[8];
    int gl = tid >> 6;                 // 0..3
#pragma unroll
    for (int pass = 0; pass < NG / 4; ++pass) {
        int g = pass * 4 + gl;
        float mxv  = udec(g_z.maxk[g * CH + c]);
        float mean = g_z.sum[g * CH + c] / fmaxf(g_z.cnt[g], 1.0f);
        float v = mxv * Wout[c] + mean * Wout[CH + c];
#pragma unroll
        for (int o = 16; o > 0; o >>= 1) v += __shfl_down_sync(0xFFFFFFFFu, v, o);
        if ((tid & 31) == 0) sh[tid >> 5] = v;
        __syncthreads();
        if (tid < 4) out[pass * 4 + tid] = sh[2 * tid] + sh[2 * tid + 1] + bout[0];
        __syncthreads();
    }
}

// ---------------- launch -------------------------------------------------------
extern "C" void kernel_launch(void* const* d_in, const int* in_sizes, int n_in,
                              void* d_out, int out_size) {
    const float* x     = (const float*)d_in[0];
    const int*   ei    = (const int*)  d_in[1];
    const float* ea    = (const float*)d_in[2];
    const int*   batch = (const int*)  d_in[3];
    const float* W0 = (const float*)d_in[4];  const float* b0 = (const float*)d_in[5];
    const float* W1 = (const float*)d_in[6];  const float* b1 = (const float*)d_in[7];
    const float* W2 = (const float*)d_in[8];  const float* b2 = (const float*)d_in[9];
    const float* W3 = (const float*)d_in[10]; const float* b3 = (const float*)d_in[11];
    const float* Wout = (const float*)d_in[12];
    const float* bout = (const float*)d_in[13];
    float* out = (float*)d_out;

    void* z_addr = nullptr;
    cudaGetSymbolAddress(&z_addr, g_z);

    const int gather_blocks = (NN * 32 + TB - 1) / TB;        // 6250

    cudaMemsetAsync(z_addr, 0, sizeof(ZeroBlk), 0);

    // layer-0 GEMM (unscaled fp32 out) fused with degree accumulation (4 edges/thread)
    k_gemm<INCH, false, true, true><<<GTILES + EB4, TB>>>(x, W0, ei, ea);
    k_scan_block<<<NB, SCAN_B>>>();
    // fused: CSR place (4 edges/thread) + layer-0 dinv scale
    k_scale_place<<<EB4 + SCALE_BLOCKS, TB>>>(ei, ea);
    k_gather<<<gather_blocks, TB>>>(b0);

    // layers 1..3: 64 -> 64 from g_act (already tanh'd), dinv applied in epilogue
    k_gemm<CH, true, false, false><<<GTILES, TB>>>(nullptr, W1, nullptr, nullptr);
    k_gather<<<gather_blocks, TB>>>(b1);
    k_gemm<CH, true, false, false><<<GTILES, TB>>>(nullptr, W2, nullptr, nullptr);
    k_gather<<<gather_blocks, TB>>>(b2);
    k_gemm<CH, true, false, false><<<GTILES, TB>>>(nullptr, W3, nullptr, nullptr);
    k_gather<<<gather_blocks, TB>>>(b3);

    k_pool<<<GTILES, TB>>>(batch, Wout, bout, out);
}

// round 17
// speedup vs baseline: 1.0824x; 1.0824x over previous
#include <cuda_runtime.h>
#include <cuda_fp16.h>
#include <cstdint>

#define NN   50000
#define NE   800000
#define NG   64
#define CH   64
#define INCH 128
#define SCAN_B 1024
#define NB   ((NN + SCAN_B - 1) / SCAN_B)   // 49
#define TB   256
#define GTILES ((NN + 63) / 64)             // 782
#define EB4  ((NE + TB * 4 - 1) / (TB * 4)) // 782 edge-blocks at 4 edges/thread
#define SCALE_BLOCKS ((NN * 16 + TB - 1) / TB)  // 3125

// ---------------- scratch (static device globals; no allocation) -------------
struct ZeroBlk {
    unsigned long long pd[NN];          // count<<40 | wdeg fixed-point
    unsigned maxk[NG * CH];             // ukey-max accumulator (0 = -inf)
    float    sum[NG * CH];
    float    cnt[NG];
    unsigned done;
};
__device__ ZeroBlk g_z;
__device__ float g_dinv[NN];
__device__ int   g_rowptr[NN + 1];
__device__ int   g_fill[NN];
__device__ int   g_bsum[64];
__device__ int2  g_edge[NE];                   // CSR-sorted (src, w-bits)
__device__ __align__(16) __half g_h[NN * CH];  // h' = dinv * (act @ W), fp16
__device__ __align__(16) float g_act[NN * CH]; // tanh(layer output), fp32

// ---------------- helpers ----------------------------------------------------
// tanh = 1 - 2/(1+e^{2x}); exact limits at +-inf, ~1e-7 abs err. 6 instrs.
__device__ __forceinline__ float acc_tanh(float x) {
    float t = __expf(2.0f * x);
    return 1.0f - __fdividef(2.0f, t + 1.0f);
}
__device__ __forceinline__ unsigned ukey(float f) {
    unsigned u = __float_as_uint(f);
    return (u & 0x80000000u) ? ~u : (u | 0x80000000u);
}
__device__ __forceinline__ float udec(unsigned u) {
    return __uint_as_float((u & 0x80000000u) ? (u & 0x7FFFFFFFu) : ~u);
}

#define FMA2(d, a, b) asm("fma.rn.f32x2 %0, %1, %2, %0;" : "+l"(d) : "l"(a), "l"(b))
__device__ __forceinline__ unsigned long long pack2(float x) {
    unsigned long long r;
    unsigned xi = __float_as_uint(x);
    asm("mov.b64 %0, {%1, %1};" : "=l"(r) : "r"(xi));
    return r;
}
__device__ __forceinline__ float2 unpack2(unsigned long long v) {
    unsigned lo, hi;
    asm("mov.b64 {%0, %1}, %2;" : "=r"(lo), "=r"(hi) : "l"(v));
    return make_float2(__uint_as_float(lo), __uint_as_float(hi));
}
__device__ __forceinline__ unsigned h2_to_u(__half2 h) {
    return *reinterpret_cast<unsigned*>(&h);
}
__device__ __forceinline__ __half2 u_to_h2(unsigned u) {
    return *reinterpret_cast<__half2*>(&u);
}

// ---------------- preprocessing ----------------------------------------------
__global__ void k_scan_block() {
    __shared__ int wsum[32];
    int tid = threadIdx.x;
    int i   = blockIdx.x * SCAN_B + tid;
    int lane = tid & 31, wid = tid >> 5;
    unsigned long long pd = (i < NN) ? g_z.pd[i] : 0ull;
    int v = (int)(pd >> 40);
    int s = v;
#pragma unroll
    for (int o = 1; o < 32; o <<= 1) {
        int t = __shfl_up_sync(0xFFFFFFFFu, s, o);
        if (lane >= o) s += t;
    }
    if (lane == 31) wsum[wid] = s;
    __syncthreads();
    if (wid == 0) {
        int ws = wsum[lane];
#pragma unroll
        for (int o = 1; o < 32; o <<= 1) {
            int t = __shfl_up_sync(0xFFFFFFFFu, ws, o);
            if (lane >= o) ws += t;
        }
        wsum[lane] = ws;
    }
    __syncthreads();
    int off = wid ? wsum[wid - 1] : 0;
    if (i < NN) {
        int rp = off + s - v;          // exclusive, pre-carry
        g_rowptr[i] = rp;
        g_fill[i]   = rp;
        float wdeg = (float)(pd & ((1ull << 40) - 1ull)) * (1.0f / 2097152.0f);
        g_dinv[i] = rsqrtf(wdeg + 1.0f);   // +1 self-loop weight
    }
    if (tid == SCAN_B - 1) g_bsum[blockIdx.x] = off + s;
}

// fused: blocks [0, EB4) place edges (4/thread, MLP-deep); rest do layer-0 scale.
__global__ void k_scale_place(const int* __restrict__ ei, const float* __restrict__ w) {
    int tid = threadIdx.x;
    if (blockIdx.x < EB4) {
        __shared__ int sc[64];
        if (tid < 32) {
            int v0 = (2 * tid     < NB) ? g_bsum[2 * tid]     : 0;
            int v1 = (2 * tid + 1 < NB) ? g_bsum[2 * tid + 1] : 0;
            int p = v0 + v1;
            int s = p;
#pragma unroll
            for (int o = 1; o < 32; o <<= 1) {
                int t = __shfl_up_sync(0xFFFFFFFFu, s, o);
                if (tid >= o) s += t;
            }
            sc[2 * tid]     = s - p;
            sc[2 * tid + 1] = s - p + v0;
        }
        __syncthreads();

        int base = blockIdx.x * (TB * 4) + tid;
        int src[4], dst[4]; float wv[4]; bool ok[4];
#pragma unroll
        for (int i = 0; i < 4; ++i) {
            int e = base + i * TB;
            ok[i] = (e < NE);
            if (ok[i]) { src[i] = ei[e]; dst[i] = ei[NE + e]; wv[i] = w[e]; }
        }
        int pos[4];
#pragma unroll
        for (int i = 0; i < 4; ++i)
            if (ok[i]) pos[i] = atomicAdd(&g_fill[dst[i]], 1) + sc[dst[i] >> 10];
#pragma unroll
        for (int i = 0; i < 4; ++i)
            if (ok[i]) g_edge[pos[i]] = make_int2(src[i], __float_as_int(wv[i]));

        // finalize rowptr (carry applied exactly once; EB4*TB = 200192 >= NN)
        int gt = blockIdx.x * TB + tid;
        if (gt < NN) g_rowptr[gt] += sc[gt >> 10];
        if (gt == 0) g_rowptr[NN] = NE;
    } else {
        // layer-0 deferred scale: g_h = fp16(dinv * g_act)
        int i = (blockIdx.x - EB4) * TB + tid;
        if (i >= NN * 16) return;
        int node = i >> 4;
        int c4 = (i & 15) * 4;
        float dv = g_dinv[node];
        float4 v = *(const float4*)(g_act + (size_t)node * CH + c4);
        uint2 st;
        st.x = h2_to_u(__float22half2_rn(make_float2(v.x * dv, v.y * dv)));
        st.y = h2_to_u(__float22half2_rn(make_float2(v.z * dv, v.w * dv)));
        *(uint2*)(g_h + (size_t)node * CH + c4) = st;
    }
}

// ------- GEMM (full-K single-stage smem, f32x2 FMA) ----------------------------
// FUSE_PRE: blocks >= GTILES run degree accumulation (4 edges/thread).
// RAW_OUT: write unscaled fp32 h to g_act (layer 0; dinv applied by k_scale_place).
template <int K, bool FROM_ACT, bool FUSE_PRE, bool RAW_OUT>
__global__ void __launch_bounds__(256, (K == 128 ? 3 : 4))
k_gemm(const float* __restrict__ in, const float* __restrict__ W,
       const int* __restrict__ ei, const float* __restrict__ ea) {
    constexpr int KP = K + 4;                 // padded A stride (16B multiple)
    __shared__ __align__(16) float sA[64 * KP];
    __shared__ __align__(16) float sW[K * 64];

    const int tid = threadIdx.x;

    if (FUSE_PRE && blockIdx.x >= GTILES) {
        int base = (blockIdx.x - GTILES) * (TB * 4) + tid;
        int dst[4]; unsigned long long v[4]; bool ok[4];
#pragma unroll
        for (int i = 0; i < 4; ++i) {
            int e = base + i * TB;
            ok[i] = (e < NE);
            if (ok[i]) {
                dst[i] = ei[NE + e];
                v[i] = (1ull << 40) |
                    (unsigned long long)__float2uint_rn(ea[e] * 2097152.0f);
            }
        }
#pragma unroll
        for (int i = 0; i < 4; ++i)
            if (ok[i]) atomicAdd(&g_z.pd[dst[i]], v[i]);
        return;
    }

    const int row0 = blockIdx.x * 64;
    const int rowg = tid >> 4;    // 0..15, 4 rows each
    const int colg = tid & 15;    // 0..15, 4 cols each

    const float* A = FROM_ACT ? (const float*)g_act : in;

    // stage full A tile (64 x K) and W (K x 64): deep MLP, one sync
#pragma unroll
    for (int idx = tid; idx < 64 * (K / 4); idx += TB) {
        int rr = idx / (K / 4), k4 = (idx % (K / 4)) * 4;
        int grow = row0 + rr;
        float4 v = make_float4(0.f, 0.f, 0.f, 0.f);
        if (grow < NN) v = *(const float4*)(A + (size_t)grow * K + k4);
        *(float4*)(sA + rr * KP + k4) = v;
    }
#pragma unroll
    for (int idx = tid; idx < K * 16; idx += TB) {
        int rr = idx >> 4, c4 = (idx & 15) * 4;
        *(float4*)(sW + rr * 64 + c4) = *(const float4*)(W + (size_t)rr * 64 + c4);
    }
    __syncthreads();

    unsigned long long acc[4][2] = {{0ull,0ull},{0ull,0ull},{0ull,0ull},{0ull,0ull}};

#pragma unroll
    for (int k = 0; k < K; k += 4) {
        float4 a0 = *(const float4*)(sA + (rowg * 4 + 0) * KP + k);
        float4 a1 = *(const float4*)(sA + (rowg * 4 + 1) * KP + k);
        float4 a2 = *(const float4*)(sA + (rowg * 4 + 2) * KP + k);
        float4 a3 = *(const float4*)(sA + (rowg * 4 + 3) * KP + k);
#pragma unroll
        for (int j = 0; j < 4; ++j) {
            const ulonglong2 wv = *(const ulonglong2*)(sW + (k + j) * 64 + colg * 4);
            float e0 = j == 0 ? a0.x : j == 1 ? a0.y : j == 2 ? a0.z : a0.w;
            float e1 = j == 0 ? a1.x : j == 1 ? a1.y : j == 2 ? a1.z : a1.w;
            float e2 = j == 0 ? a2.x : j == 1 ? a2.y : j == 2 ? a2.z : a2.w;
            float e3 = j == 0 ? a3.x : j == 1 ? a3.y : j == 2 ? a3.z : a3.w;
            unsigned long long p0 = pack2(e0), p1 = pack2(e1);
            unsigned long long p2 = pack2(e2), p3 = pack2(e3);
            FMA2(acc[0][0], p0, wv.x); FMA2(acc[0][1], p0, wv.y);
            FMA2(acc[1][0], p1, wv.x); FMA2(acc[1][1], p1, wv.y);
            FMA2(acc[2][0], p2, wv.x); FMA2(acc[2][1], p2, wv.y);
            FMA2(acc[3][0], p3, wv.x); FMA2(acc[3][1], p3, wv.y);
        }
    }

    int row = row0 + rowg * 4;
#pragma unroll
    for (int i = 0; i < 4; ++i) {
        if (row + i < NN) {
            float2 lo = unpack2(acc[i][0]);
            float2 hi = unpack2(acc[i][1]);
            if (RAW_OUT) {
                *(float4*)(g_act + (size_t)(row + i) * CH + colg * 4) =
                    make_float4(lo.x, lo.y, hi.x, hi.y);
            } else {
                float dv = g_dinv[row + i];
                lo.x *= dv; lo.y *= dv; hi.x *= dv; hi.y *= dv;
                uint2 st;
                st.x = h2_to_u(__float22half2_rn(lo));
                st.y = h2_to_u(__float22half2_rn(hi));
                *(uint2*)(g_h + (size_t)(row + i) * CH + colg * 4) = st;
            }
        }
    }
}

// --- gather: act[i] = tanh(b + dv_i*(sum_e w_e*h'[src] + h'[i])) ---------------
// one warp per node; 2 edges/iter via direct half-warp reads (r14 optimum:
// rolled loop, 32 regs, occ ~82%). __ldg NC hints, register-neutral.
__global__ void k_gather(const float* __restrict__ b) {
    int warp = (blockIdx.x * blockDim.x + threadIdx.x) >> 5;
    int lane = threadIdx.x & 31;
    if (warp >= NN) return;
    const int node = warp;
    const int beg  = g_rowptr[node];
    const int deg  = g_rowptr[node + 1] - beg;
    const int half = lane >> 4;
    const int c4   = (lane & 15) * 4;
    const __half* __restrict__ hb = g_h;

    float ax = 0.f, ay = 0.f, az = 0.f, aw = 0.f;
    const int np = deg >> 1;
#pragma unroll 4
    for (int j = 0; j < np; ++j) {
        int2 e = __ldg(&g_edge[beg + 2 * j + half]);
        float ne = __int_as_float(e.y);
        uint2 hv = __ldg((const uint2*)(hb + (size_t)e.x * CH + c4));
        float2 f0 = __half22float2(u_to_h2(hv.x));
        float2 f1 = __half22float2(u_to_h2(hv.y));
        ax += ne * f0.x; ay += ne * f0.y; az += ne * f1.x; aw += ne * f1.y;
    }
    if (deg & 1) {
        int2 e = __ldg(&g_edge[beg + deg - 1]);
        float ne = half ? 0.0f : __int_as_float(e.y);   // avoid double count
        uint2 hv = __ldg((const uint2*)(hb + (size_t)e.x * CH + c4));
        float2 f0 = __half22float2(u_to_h2(hv.x));
        float2 f1 = __half22float2(u_to_h2(hv.y));
        ax += ne * f0.x; ay += ne * f0.y; az += ne * f1.x; aw += ne * f1.y;
    }
    ax += __shfl_xor_sync(0xFFFFFFFFu, ax, 16);
    ay += __shfl_xor_sync(0xFFFFFFFFu, ay, 16);
    az += __shfl_xor_sync(0xFFFFFFFFu, az, 16);
    aw += __shfl_xor_sync(0xFFFFFFFFu, aw, 16);

    if (half == 0) {
        float dv = g_dinv[node];
        uint2 hu = __ldg((const uint2*)(hb + (size_t)node * CH + c4));
        float2 h0 = __half22float2(u_to_h2(hu.x));
        float2 h1 = __half22float2(u_to_h2(hu.y));
        float4 bb = *(const float4*)(b + c4);
        float4 o;
        o.x = acc_tanh(bb.x + dv * (ax + h0.x));
        o.y = acc_tanh(bb.y + dv * (ay + h0.y));
        o.z = acc_tanh(bb.z + dv * (az + h1.x));
        o.w = acc_tanh(bb.w + dv * (aw + h1.y));
        *(float4*)(g_act + (size_t)node * CH + c4) = o;
    }
}

// ---------------- pooling + fused head (g_z memset to 0) -----------------------
__device__ __forceinline__ void pool_flush(int g, int c, float mx, float sm, int cnt) {
    if (g < 0) return;
    atomicMax(&g_z.maxk[g * CH + c], ukey(mx));
    atomicAdd(&g_z.sum[g * CH + c], sm);
    if (c == 0) atomicAdd(&g_z.cnt[g], (float)cnt);
}

__global__ void k_pool(const int* __restrict__ batch,
                       const float* __restrict__ Wout,
                       const float* __restrict__ bout,
                       float* __restrict__ out) {
    int tid = threadIdx.x;
    int c  = tid & 63;
    int rs = tid >> 6;           // 0..3
    int base = blockIdx.x * 64;

    int curg = -1; float mx = -3.4e38f, sm = 0.0f; int cnt = 0;
    for (int r = rs; r < 64; r += 4) {
        int node = base + r;
        if (node >= NN) break;
        int g = batch[node];
        float v = g_act[(size_t)node * CH + c];
        if (g != curg) {
            pool_flush(curg, c, mx, sm, cnt);
            curg = g; mx = v; sm = v; cnt = 1;
        } else {
            mx = fmaxf(mx, v); sm += v; cnt++;
        }
    }
    pool_flush(curg, c, mx, sm, cnt);

    // last-block head
    __threadfence();
    __shared__ int s_last;
    __syncthreads();
    if (tid == 0) {
        unsigned t = atomicAdd(&g_z.done, 1u);
        s_last = (t == gridDim.x - 1) ? 1 : 0;
    }
    __syncthreads();
    if (!s_last) return;
    __threadfence();

    __shared__ float sh[8];
    int gl = tid >> 6;                 // 0..3
#pragma unroll
    for (int pass = 0; pass < NG / 4; ++pass) {
        int g = pass * 4 + gl;
        float mxv  = udec(g_z.maxk[g * CH + c]);
        float mean = g_z.sum[g * CH + c] / fmaxf(g_z.cnt[g], 1.0f);
        float v = mxv * Wout[c] + mean * Wout[CH + c];
#pragma unroll
        for (int o = 16; o > 0; o >>= 1) v += __shfl_down_sync(0xFFFFFFFFu, v, o);
        if ((tid & 31) == 0) sh[tid >> 5] = v;
        __syncthreads();
        if (tid < 4) out[pass * 4 + tid] = sh[2 * tid] + sh[2 * tid + 1] + bout[0];
        __syncthreads();
    }
}

// ---------------- launch -------------------------------------------------------
extern "C" void kernel_launch(void* const* d_in, const int* in_sizes, int n_in,
                              void* d_out, int out_size) {
    const float* x     = (const float*)d_in[0];
    const int*   ei    = (const int*)  d_in[1];
    const float* ea    = (const float*)d_in[2];
    const int*   batch = (const int*)  d_in[3];
    const float* W0 = (const float*)d_in[4];  const float* b0 = (const float*)d_in[5];
    const float* W1 = (const float*)d_in[6];  const float* b1 = (const float*)d_in[7];
    const float* W2 = (const float*)d_in[8];  const float* b2 = (const float*)d_in[9];
    const float* W3 = (const float*)d_in[10]; const float* b3 = (const float*)d_in[11];
    const float* Wout = (const float*)d_in[12];
    const float* bout = (const float*)d_in[13];
    float* out = (float*)d_out;

    void* z_addr = nullptr;
    cudaGetSymbolAddress(&z_addr, g_z);

    const int gather_blocks = (NN * 32 + TB - 1) / TB;        // 6250

    cudaMemsetAsync(z_addr, 0, sizeof(ZeroBlk), 0);

    // layer-0 GEMM (unscaled fp32 out) fused with degree accumulation (4 edges/thread)
    k_gemm<INCH, false, true, true><<<GTILES + EB4, TB>>>(x, W0, ei, ea);
    k_scan_block<<<NB, SCAN_B>>>();
    // fused: CSR place (4 edges/thread) + layer-0 dinv scale
    k_scale_place<<<EB4 + SCALE_BLOCKS, TB>>>(ei, ea);
    k_gather<<<gather_blocks, TB>>>(b0);

    // layers 1..3: 64 -> 64 from g_act (already tanh'd), dinv applied in epilogue
    k_gemm<CH, true, false, false><<<GTILES, TB>>>(nullptr, W1, nullptr, nullptr);
    k_gather<<<gather_blocks, TB>>>(b1);
    k_gemm<CH, true, false, false><<<GTILES, TB>>>(nullptr, W2, nullptr, nullptr);
    k_gather<<<gather_blocks, TB>>>(b2);
    k_gemm<CH, true, false, false><<<GTILES, TB>>>(nullptr, W3, nullptr, nullptr);
    k_gather<<<gather_blocks, TB>>>(b3);

    k_pool<<<GTILES, TB>>>(batch, Wout, bout, out);
}